// round 7
// baseline (speedup 1.0000x reference)
#include <cuda_runtime.h>
#include <cstdint>

// ============================================================================
// Router gate: x [32768, 2048] f32, w [64, 2048] f32.
// logits = x @ w^T ; probs = softmax ; top-8 vals + indices.
// Out: [probs N*64 | top_vals N*8 | indices(float) N*8]
//
// mma m16n8k8 TF32, 2-way split (x=xh+xm, w=wh+wm):
//   xh*wh -> chunk accumulator, rebased every k32 into master via RN FADD
//   xh*wm + xm*wh -> separate small-magnitude accumulator
// R7: x pre-split ONCE per element into smem as (h,m) float2 pairs
//     (4x less cvt); MMAs reordered so dependent pairs are 8 apart.
// ============================================================================

#define D 2048
#define TB 128            // tokens per CTA
#define NCH 64            // k32 chunks
#define BSTEP 4096        // B frag bytes per step
#define BCHUNK 16384      // 4 steps
#define XSTRIDE 288       // bytes per x row: 36 float2 (36 % 16 == 4 -> CF)
#define XCHUNK 36864      // 128 rows * 288
#define XB 32768          // x region base (after 2 B stages)
#define EPI_STRIDE 68
#define SMEM_SZ (XB + 2 * XCHUNK)   // 106496

// weights split into tf32 h/m, HMMA B-fragment order:
// [step(256)][tile(8)][lane(32)] x uint4(bh0, bh1, bm0, bm1)
__device__ __align__(16) unsigned char g_bfrag[256 * BSTEP];

static __device__ __forceinline__ uint32_t smem_u32(const void* p) {
    uint32_t a;
    asm("{ .reg .u64 t; cvta.to.shared.u64 t, %1; cvt.u32.u64 %0, t; }"
        : "=r"(a) : "l"(p));
    return a;
}
static __device__ __forceinline__ void split2(float v, uint32_t& h, uint32_t& m) {
    asm("cvt.rna.tf32.f32 %0, %1;" : "=r"(h) : "f"(v));
    float r = v - __uint_as_float(h);
    asm("cvt.rna.tf32.f32 %0, %1;" : "=r"(m) : "f"(r));
}

#define MMA(d, a, b0_, b1_) \
    asm volatile("mma.sync.aligned.m16n8k8.row.col.f32.tf32.tf32.f32 " \
        "{%0,%1,%2,%3}, {%4,%5,%6,%7}, {%8,%9}, {%0,%1,%2,%3};" \
        : "+f"((d)[0]), "+f"((d)[1]), "+f"((d)[2]), "+f"((d)[3]) \
        : "r"((a)[0]), "r"((a)[1]), "r"((a)[2]), "r"((a)[3]), "r"(b0_), "r"(b1_))
#define MMA_ZC(d, a, b0_, b1_) \
    asm volatile("mma.sync.aligned.m16n8k8.row.col.f32.tf32.tf32.f32 " \
        "{%0,%1,%2,%3}, {%4,%5,%6,%7}, {%8,%9}, {%10,%10,%10,%10};" \
        : "=f"((d)[0]), "=f"((d)[1]), "=f"((d)[2]), "=f"((d)[3]) \
        : "r"((a)[0]), "r"((a)[1]), "r"((a)[2]), "r"((a)[3]), "r"(b0_), "r"(b1_), \
          "f"(0.0f))

#define CP16(s, g) \
    asm volatile("cp.async.cg.shared.global [%0], [%1], 16;" :: "r"(s), "l"(g) : "memory")
#define CP_COMMIT() asm volatile("cp.async.commit_group;" ::: "memory")
#define CP_WAIT1()  asm volatile("cp.async.wait_group 1;" ::: "memory")
#define CP_WAIT0()  asm volatile("cp.async.wait_group 0;" ::: "memory")
#define LDS128(v, a) \
    asm volatile("ld.shared.v4.b32 {%0,%1,%2,%3}, [%4];" \
        : "=r"((v).x), "=r"((v).y), "=r"((v).z), "=r"((v).w) : "r"(a))
#define LDS64(v, a) \
    asm volatile("ld.shared.v2.b32 {%0,%1}, [%2];" : "=r"((v).x), "=r"((v).y) : "r"(a))
#define STS128(a, v0, v1, v2, v3) \
    asm volatile("st.shared.v4.b32 [%0], {%1,%2,%3,%4};" \
        :: "r"(a), "r"(v0), "r"(v1), "r"(v2), "r"(v3) : "memory")

// ---------------- weight prep ----------------
__global__ void prep_bfrag(const float* __restrict__ w) {
    int i = blockIdx.x * blockDim.x + threadIdx.x;   // (step*8 + tile)*32 + lane
    if (i >= 256 * 8 * 32) return;
    int lane = i & 31;
    int tile = (i >> 5) & 7;
    int step = i >> 8;
    int e = tile * 8 + (lane >> 2);
    int tq = lane & 3;
    int k0 = step * 8;
    const float* wr = w + (size_t)e * D;
    uint32_t h0, m0, h1, m1;
    split2(wr[k0 + tq],     h0, m0);
    split2(wr[k0 + tq + 4], h1, m1);
    *reinterpret_cast<uint4*>(g_bfrag + step * BSTEP + tile * 512 + lane * 16) =
        make_uint4(h0, h1, m0, m1);
}

// split 8 floats and store as interleaved (h,m) pairs: 4 x STS.128
static __device__ __forceinline__ void sts_split8(uint32_t dst, float4 a, float4 b) {
    uint32_t h0, m0, h1, m1, h2, m2, h3, m3;
    split2(a.x, h0, m0); split2(a.y, h1, m1);
    split2(a.z, h2, m2); split2(a.w, h3, m3);
    STS128(dst,      h0, m0, h1, m1);
    STS128(dst + 16, h2, m2, h3, m3);
    split2(b.x, h0, m0); split2(b.y, h1, m1);
    split2(b.z, h2, m2); split2(b.w, h3, m3);
    STS128(dst + 32, h0, m0, h1, m1);
    STS128(dst + 48, h2, m2, h3, m3);
}

// ---------------- main fused kernel ----------------
__global__ void __launch_bounds__(512, 1)
moe_gate(const float* __restrict__ x, float* __restrict__ out, int Ntok) {
    extern __shared__ __align__(16) float smemf[];
    const uint32_t sbase = smem_u32(smemf);
    const int tid = threadIdx.x;
    const int wid = tid >> 5;
    const int lane = tid & 31;
    const int g = lane >> 2;
    const int t4 = lane & 3;
    const int tg = wid >> 2;          // token group 0..3 (32 tokens)
    const int eq = wid & 3;           // expert quarter 0..3 (16 experts)
    const size_t t0 = (size_t)blockIdx.x * TB;

    float chx[4][4], ms[4][4], cc[4][4];   // [mhalf*2 + ntile][4]
    #pragma unroll
    for (int i = 0; i < 4; ++i)
        #pragma unroll
        for (int j = 0; j < 4; ++j) { ms[i][j] = 0.0f; cc[i][j] = 0.0f; }

    // x staging role: thread -> (row, 8 consecutive k)
    const int xrow = tid >> 2;
    const int xkq = (tid & 3) * 8;
    const float* xgp = x + (t0 + xrow) * D + xkq;
    const uint32_t xsts0 = sbase + XB + xrow * XSTRIDE + xkq * 8;

    // prologue: LDG chunk0 x, split+STS into stage 0, LDG chunk1, stage B0
    {
        float4 a = *reinterpret_cast<const float4*>(xgp);
        float4 b = *reinterpret_cast<const float4*>(xgp + 4);
        sts_split8(xsts0, a, b);
    }
    float4 xr0 = *reinterpret_cast<const float4*>(xgp + 32);
    float4 xr1 = *reinterpret_cast<const float4*>(xgp + 36);
    CP16(sbase + tid * 16,         g_bfrag + tid * 16);
    CP16(sbase + (tid + 512) * 16, g_bfrag + (tid + 512) * 16);
    CP_COMMIT();

    // fragment gather base (byte): rows {.,+8,+16,+24} at +2304 steps
    const uint32_t xfrag0 = sbase + XB + (tg * 32 + g) * XSTRIDE + t4 * 8;

    for (int ch = 0; ch < NCH; ++ch) {
        if (ch + 1 < NCH) {
            const unsigned char* bsrc = g_bfrag + (size_t)(ch + 1) * BCHUNK;
            uint32_t bd = sbase + ((ch + 1) & 1) * BCHUNK;
            CP16(bd + tid * 16,         bsrc + tid * 16);
            CP16(bd + (tid + 512) * 16, bsrc + (tid + 512) * 16);
            CP_COMMIT();
            CP_WAIT1();
        } else {
            CP_WAIT0();
        }
        __syncthreads();   // B(ch) + X(ch) visible to all

        const uint32_t bstg = sbase + (ch & 1) * BCHUNK + eq * 1024 + lane * 16;
        const uint32_t xstg = xfrag0 + (ch & 1) * XCHUNK;

        #pragma unroll
        for (int s4 = 0; s4 < 4; ++s4) {
            const uint32_t xp = xstg + s4 * 64;
            uint2 p0, p1, p2, p3, p4, p5, p6, p7;
            LDS64(p0, xp);                  // row g,    k t4
            LDS64(p1, xp + 32);             // row g,    k t4+4
            LDS64(p2, xp + 2304);           // row g+8
            LDS64(p3, xp + 2304 + 32);
            LDS64(p4, xp + 4608);           // row g+16
            LDS64(p5, xp + 4608 + 32);
            LDS64(p6, xp + 6912);           // row g+24
            LDS64(p7, xp + 6912 + 32);
            uint32_t Ah0[4] = {p0.x, p2.x, p1.x, p3.x};
            uint32_t Am0[4] = {p0.y, p2.y, p1.y, p3.y};
            uint32_t Ah1[4] = {p4.x, p6.x, p5.x, p7.x};
            uint32_t Am1[4] = {p4.y, p6.y, p5.y, p7.y};

            const uint32_t bb = bstg + s4 * BSTEP;
            uint4 b0, b1;
            LDS128(b0, bb);
            LDS128(b1, bb + 512);

            // corrections (first half) -- independent of chx
            MMA(cc[0], Am0, b0.x, b0.y);
            MMA(cc[1], Am0, b1.x, b1.y);
            MMA(cc[2], Am1, b0.x, b0.y);
            MMA(cc[3], Am1, b1.x, b1.y);
            // hh chunk terms (restart onto zero C at chunk head)
            if (s4 == 0) {
                MMA_ZC(chx[0], Ah0, b0.x, b0.y);
                MMA_ZC(chx[1], Ah0, b1.x, b1.y);
                MMA_ZC(chx[2], Ah1, b0.x, b0.y);
                MMA_ZC(chx[3], Ah1, b1.x, b1.y);
            } else {
                MMA(chx[0], Ah0, b0.x, b0.y);
                MMA(chx[1], Ah0, b1.x, b1.y);
                MMA(chx[2], Ah1, b0.x, b0.y);
                MMA(chx[3], Ah1, b1.x, b1.y);
            }
            // corrections (second half) -- dependent pairs now 8 MMAs apart
            MMA(cc[0], Ah0, b0.z, b0.w);
            MMA(cc[1], Ah0, b1.z, b1.w);
            MMA(cc[2], Ah1, b0.z, b0.w);
            MMA(cc[3], Ah1, b1.z, b1.w);
        }

        // stage next x chunk: split regs (chunk ch+1 data), LDG chunk ch+2
        if (ch + 1 < NCH) {
            sts_split8(xsts0 + ((ch + 1) & 1) * XCHUNK, xr0, xr1);
            if (ch + 2 < NCH) {
                const float* nx = xgp + (size_t)(ch + 2) * 32;
                xr0 = *reinterpret_cast<const float4*>(nx);
                xr1 = *reinterpret_cast<const float4*>(nx + 4);
            }
        }

        // rebase: master += chunk (RN fp32, unbiased)
        #pragma unroll
        for (int i = 0; i < 4; ++i)
            #pragma unroll
            for (int j = 0; j < 4; ++j) ms[i][j] += chx[i][j];
        __syncthreads();   // all reads of stage (ch&1) done before overwrite
    }

    // -------- epilogue: logits -> smem, thread-per-token softmax + top-8 ----
    float* L = smemf;   // [128][EPI_STRIDE]
    #pragma unroll
    for (int j = 0; j < 2; ++j) {
        int n0 = eq * 16 + j * 8 + 2 * t4;
        int r0 = tg * 32 + g;
        *reinterpret_cast<float2*>(L + r0 * EPI_STRIDE + n0) =
            make_float2(ms[j][0] + cc[j][0], ms[j][1] + cc[j][1]);
        *reinterpret_cast<float2*>(L + (r0 + 8) * EPI_STRIDE + n0) =
            make_float2(ms[j][2] + cc[j][2], ms[j][3] + cc[j][3]);
        *reinterpret_cast<float2*>(L + (r0 + 16) * EPI_STRIDE + n0) =
            make_float2(ms[2 + j][0] + cc[2 + j][0], ms[2 + j][1] + cc[2 + j][1]);
        *reinterpret_cast<float2*>(L + (r0 + 24) * EPI_STRIDE + n0) =
            make_float2(ms[2 + j][2] + cc[2 + j][2], ms[2 + j][3] + cc[2 + j][3]);
    }
    __syncthreads();

    if (tid < TB) {
        float pv[64];
        const float* Lr = L + tid * EPI_STRIDE;
        #pragma unroll
        for (int c = 0; c < 16; ++c) {
            float4 v = *reinterpret_cast<const float4*>(Lr + 4 * c);
            pv[4 * c] = v.x; pv[4 * c + 1] = v.y;
            pv[4 * c + 2] = v.z; pv[4 * c + 3] = v.w;
        }
        float mx = pv[0];
        #pragma unroll
        for (int c = 1; c < 64; ++c) mx = fmaxf(mx, pv[c]);
        float s = 0.0f;
        #pragma unroll
        for (int c = 0; c < 64; ++c) { pv[c] = __expf(pv[c] - mx); s += pv[c]; }
        float inv = 1.0f / s;
        #pragma unroll
        for (int c = 0; c < 64; ++c) pv[c] *= inv;

        const size_t gt = t0 + tid;
        float* pr = out + gt * 64;
        #pragma unroll
        for (int c = 0; c < 16; ++c)
            *reinterpret_cast<float4*>(pr + 4 * c) =
                make_float4(pv[4 * c], pv[4 * c + 1], pv[4 * c + 2], pv[4 * c + 3]);

        // top-8 insertion; strict '>' keeps smaller index on ties (lax.top_k)
        float tv[8]; int ti[8];
        #pragma unroll
        for (int r = 0; r < 8; ++r) { tv[r] = -1.0f; ti[r] = 0; }
        #pragma unroll
        for (int j = 0; j < 64; ++j) {
            float v = pv[j];
            if (v > tv[7]) {
                tv[7] = v; ti[7] = j;
                #pragma unroll
                for (int q = 7; q > 0; --q) {
                    bool sw = tv[q] > tv[q - 1];
                    float fv = sw ? tv[q - 1] : tv[q];
                    int   fi = sw ? ti[q - 1] : ti[q];
                    tv[q - 1] = sw ? tv[q] : tv[q - 1];
                    ti[q - 1] = sw ? ti[q] : ti[q - 1];
                    tv[q] = fv; ti[q] = fi;
                }
            }
        }
        const size_t tvo = (size_t)Ntok * 64;
        const size_t ixo = tvo + (size_t)Ntok * 8;
        *reinterpret_cast<float4*>(out + tvo + gt * 8)     =
            make_float4(tv[0], tv[1], tv[2], tv[3]);
        *reinterpret_cast<float4*>(out + tvo + gt * 8 + 4) =
            make_float4(tv[4], tv[5], tv[6], tv[7]);
        *reinterpret_cast<float4*>(out + ixo + gt * 8)     =
            make_float4((float)ti[0], (float)ti[1], (float)ti[2], (float)ti[3]);
        *reinterpret_cast<float4*>(out + ixo + gt * 8 + 4) =
            make_float4((float)ti[4], (float)ti[5], (float)ti[6], (float)ti[7]);
    }
}

extern "C" void kernel_launch(void* const* d_in, const int* in_sizes, int n_in,
                              void* d_out, int out_size) {
    const float* x = (const float*)d_in[0];
    const float* w = (const float*)d_in[1];
    float* out = (float*)d_out;
    int Ntok = in_sizes[0] / D;     // 32768

    cudaFuncSetAttribute(moe_gate, cudaFuncAttributeMaxDynamicSharedMemorySize, SMEM_SZ);
    prep_bfrag<<<(256 * 8 * 32 + 255) / 256, 256>>>(w);
    moe_gate<<<Ntok / TB, 512, SMEM_SZ>>>(x, out, Ntok);
}

// round 8
// speedup vs baseline: 1.2217x; 1.2217x over previous
#include <cuda_runtime.h>
#include <cstdint>

// ============================================================================
// Router gate: x [32768, 2048] f32, w [64, 2048] f32.
// logits = x @ w^T ; probs = softmax ; top-8 vals + indices.
// Out: [probs N*64 | top_vals N*8 | indices(float) N*8]
//
// mma m16n8k8 TF32, 2-way split (x=xh+xm, w=wh+wm):
//   xh*wh -> chunk accumulator, rebased every k32 into master via RN FADD
//   xh*wm + xm*wh -> separate small-magnitude accumulator
// R8: warp tile m16 x n64 (8 warps, TB=128) -> zero A-split redundancy,
//     24 MMAs per step per warp; x staged raw via cp.async (R6 style).
// ============================================================================

#define D 2048
#define TB 128            // tokens per CTA (8 warps x m16)
#define NCH 64            // k32 chunks
#define BSTEP 4096        // B frag bytes per step
#define BCHUNK 16384      // 4 steps
#define XSTRIDE 144       // bytes per x row: 36 floats (CF swizzle)
#define XCHUNK 18432      // 128 rows * 144
#define XB 32768          // x region base (after 2 B stages)
#define EPI_STRIDE 68
#define SMEM_SZ (XB + 2 * XCHUNK)   // 69632

// weights split into tf32 h/m, HMMA B-fragment order:
// [step(256)][tile(8)][lane(32)] x uint4(bh0, bh1, bm0, bm1)
__device__ __align__(16) unsigned char g_bfrag[256 * BSTEP];

static __device__ __forceinline__ uint32_t smem_u32(const void* p) {
    uint32_t a;
    asm("{ .reg .u64 t; cvta.to.shared.u64 t, %1; cvt.u32.u64 %0, t; }"
        : "=r"(a) : "l"(p));
    return a;
}
static __device__ __forceinline__ void split2(float v, uint32_t& h, uint32_t& m) {
    asm("cvt.rna.tf32.f32 %0, %1;" : "=r"(h) : "f"(v));
    float r = v - __uint_as_float(h);
    asm("cvt.rna.tf32.f32 %0, %1;" : "=r"(m) : "f"(r));
}

#define MMA(d, a, b0_, b1_) \
    asm volatile("mma.sync.aligned.m16n8k8.row.col.f32.tf32.tf32.f32 " \
        "{%0,%1,%2,%3}, {%4,%5,%6,%7}, {%8,%9}, {%0,%1,%2,%3};" \
        : "+f"((d)[0]), "+f"((d)[1]), "+f"((d)[2]), "+f"((d)[3]) \
        : "r"((a)[0]), "r"((a)[1]), "r"((a)[2]), "r"((a)[3]), "r"(b0_), "r"(b1_))
#define MMA_ZC(d, a, b0_, b1_) \
    asm volatile("mma.sync.aligned.m16n8k8.row.col.f32.tf32.tf32.f32 " \
        "{%0,%1,%2,%3}, {%4,%5,%6,%7}, {%8,%9}, {%10,%10,%10,%10};" \
        : "=f"((d)[0]), "=f"((d)[1]), "=f"((d)[2]), "=f"((d)[3]) \
        : "r"((a)[0]), "r"((a)[1]), "r"((a)[2]), "r"((a)[3]), "r"(b0_), "r"(b1_), \
          "f"(0.0f))

#define CP16(s, g) \
    asm volatile("cp.async.cg.shared.global [%0], [%1], 16;" :: "r"(s), "l"(g) : "memory")
#define CP_COMMIT() asm volatile("cp.async.commit_group;" ::: "memory")
#define CP_WAIT1()  asm volatile("cp.async.wait_group 1;" ::: "memory")
#define CP_WAIT0()  asm volatile("cp.async.wait_group 0;" ::: "memory")
#define LDS128(v, a) \
    asm volatile("ld.shared.v4.b32 {%0,%1,%2,%3}, [%4];" \
        : "=r"((v).x), "=r"((v).y), "=r"((v).z), "=r"((v).w) : "r"(a))
#define LDSF(v, a) \
    asm volatile("ld.shared.f32 %0, [%1];" : "=f"(v) : "r"(a))

// ---------------- weight prep ----------------
__global__ void prep_bfrag(const float* __restrict__ w) {
    int i = blockIdx.x * blockDim.x + threadIdx.x;   // (step*8 + tile)*32 + lane
    if (i >= 256 * 8 * 32) return;
    int lane = i & 31;
    int tile = (i >> 5) & 7;
    int step = i >> 8;
    int e = tile * 8 + (lane >> 2);
    int tq = lane & 3;
    int k0 = step * 8;
    const float* wr = w + (size_t)e * D;
    uint32_t h0, m0, h1, m1;
    split2(wr[k0 + tq],     h0, m0);
    split2(wr[k0 + tq + 4], h1, m1);
    *reinterpret_cast<uint4*>(g_bfrag + step * BSTEP + tile * 512 + lane * 16) =
        make_uint4(h0, h1, m0, m1);
}

// ---------------- main fused kernel ----------------
__global__ void __launch_bounds__(256, 1)
moe_gate(const float* __restrict__ x, float* __restrict__ out, int Ntok) {
    extern __shared__ __align__(16) float smemf[];
    const uint32_t sbase = smem_u32(smemf);
    const int tid = threadIdx.x;
    const int wid = tid >> 5;         // 0..7: token group (16 tokens)
    const int lane = tid & 31;
    const int g = lane >> 2;
    const int t4 = lane & 3;
    const size_t t0 = (size_t)blockIdx.x * TB;
    const unsigned char* xg = reinterpret_cast<const unsigned char*>(x + t0 * D);

    // [tile(8)][4]
    float chx[8][4], ms[8][4], cc[8][4];
    #pragma unroll
    for (int i = 0; i < 8; ++i)
        #pragma unroll
        for (int j = 0; j < 4; ++j) { ms[i][j] = 0.0f; cc[i][j] = 0.0f; }

    // prologue: stage chunk 0 (B 16KB + X 16KB raw -> stride-36 layout)
    #pragma unroll
    for (int p = 0; p < 4; ++p) {
        int u = tid + p * 256;
        CP16(sbase + u * 16, g_bfrag + u * 16);                      // B
        int row = u >> 3, seg = u & 7;
        CP16(sbase + XB + row * XSTRIDE + seg * 16,
             xg + (size_t)row * (D * 4) + seg * 16);                 // X
    }
    CP_COMMIT();

    // fragment gather base: row = wid*16 + g; k offsets t4, t4+4 (floats)
    const uint32_t xfrag0 = sbase + XB + (wid * 16 + g) * XSTRIDE + t4 * 4;

    for (int ch = 0; ch < NCH; ++ch) {
        if (ch + 1 < NCH) {
            const unsigned char* bsrc = g_bfrag + (size_t)(ch + 1) * BCHUNK;
            uint32_t bd = sbase + ((ch + 1) & 1) * BCHUNK;
            uint32_t xd = sbase + XB + ((ch + 1) & 1) * XCHUNK;
            size_t kb = (size_t)(ch + 1) * 128;                      // 32 floats
            #pragma unroll
            for (int p = 0; p < 4; ++p) {
                int u = tid + p * 256;
                CP16(bd + u * 16, bsrc + u * 16);
                int row = u >> 3, seg = u & 7;
                CP16(xd + row * XSTRIDE + seg * 16,
                     xg + (size_t)row * (D * 4) + kb + seg * 16);
            }
            CP_COMMIT();
            CP_WAIT1();
        } else {
            CP_WAIT0();
        }
        __syncthreads();

        const uint32_t bstg = sbase + (ch & 1) * BCHUNK + lane * 16;
        const uint32_t xstg = xfrag0 + (ch & 1) * XCHUNK;

        #pragma unroll
        for (int s4 = 0; s4 < 4; ++s4) {
            const uint32_t xp = xstg + s4 * 32;
            float x0, x1, x2, x3;
            LDSF(x0, xp);                    // row g,   k t4
            LDSF(x1, xp + 16);               // row g,   k t4+4
            LDSF(x2, xp + 8 * XSTRIDE);      // row g+8, k t4
            LDSF(x3, xp + 8 * XSTRIDE + 16); // row g+8, k t4+4

            uint32_t Ah[4], Am[4];
            split2(x0, Ah[0], Am[0]);
            split2(x2, Ah[1], Am[1]);
            split2(x1, Ah[2], Am[2]);
            split2(x3, Ah[3], Am[3]);

            const uint32_t bb = bstg + s4 * BSTEP;
            #pragma unroll
            for (int jj = 0; jj < 4; ++jj) {
                uint4 b0, b1;
                LDS128(b0, bb + (2 * jj) * 512);
                LDS128(b1, bb + (2 * jj + 1) * 512);
                MMA(cc[2 * jj],     Am, b0.x, b0.y);
                MMA(cc[2 * jj + 1], Am, b1.x, b1.y);
                if (s4 == 0) {               // chunk restart onto zero C
                    MMA_ZC(chx[2 * jj],     Ah, b0.x, b0.y);
                    MMA_ZC(chx[2 * jj + 1], Ah, b1.x, b1.y);
                } else {
                    MMA(chx[2 * jj],     Ah, b0.x, b0.y);
                    MMA(chx[2 * jj + 1], Ah, b1.x, b1.y);
                }
                MMA(cc[2 * jj],     Ah, b0.z, b0.w);
                MMA(cc[2 * jj + 1], Ah, b1.z, b1.w);
            }
        }
        // rebase: master += chunk (RN fp32, unbiased)
        #pragma unroll
        for (int i = 0; i < 8; ++i)
            #pragma unroll
            for (int j = 0; j < 4; ++j) ms[i][j] += chx[i][j];
        __syncthreads();
    }

    // -------- epilogue: logits -> smem, thread-per-token softmax + top-8 ----
    float* L = smemf;   // [128][EPI_STRIDE]
    {
        int r0 = wid * 16 + g;
        #pragma unroll
        for (int j = 0; j < 8; ++j) {
            int n0 = j * 8 + 2 * t4;
            *reinterpret_cast<float2*>(L + r0 * EPI_STRIDE + n0) =
                make_float2(ms[j][0] + cc[j][0], ms[j][1] + cc[j][1]);
            *reinterpret_cast<float2*>(L + (r0 + 8) * EPI_STRIDE + n0) =
                make_float2(ms[j][2] + cc[j][2], ms[j][3] + cc[j][3]);
        }
    }
    __syncthreads();

    if (tid < TB) {
        float pv[64];
        const float* Lr = L + tid * EPI_STRIDE;
        #pragma unroll
        for (int c = 0; c < 16; ++c) {
            float4 v = *reinterpret_cast<const float4*>(Lr + 4 * c);
            pv[4 * c] = v.x; pv[4 * c + 1] = v.y;
            pv[4 * c + 2] = v.z; pv[4 * c + 3] = v.w;
        }
        float mx = pv[0];
        #pragma unroll
        for (int c = 1; c < 64; ++c) mx = fmaxf(mx, pv[c]);
        float s = 0.0f;
        #pragma unroll
        for (int c = 0; c < 64; ++c) { pv[c] = __expf(pv[c] - mx); s += pv[c]; }
        float inv = 1.0f / s;
        #pragma unroll
        for (int c = 0; c < 64; ++c) pv[c] *= inv;

        const size_t gt = t0 + tid;
        float* pr = out + gt * 64;
        #pragma unroll
        for (int c = 0; c < 16; ++c)
            *reinterpret_cast<float4*>(pr + 4 * c) =
                make_float4(pv[4 * c], pv[4 * c + 1], pv[4 * c + 2], pv[4 * c + 3]);

        // top-8 insertion; strict '>' keeps smaller index on ties (lax.top_k)
        float tv[8]; int ti[8];
        #pragma unroll
        for (int r = 0; r < 8; ++r) { tv[r] = -1.0f; ti[r] = 0; }
        #pragma unroll
        for (int j = 0; j < 64; ++j) {
            float v = pv[j];
            if (v > tv[7]) {
                tv[7] = v; ti[7] = j;
                #pragma unroll
                for (int q = 7; q > 0; --q) {
                    bool sw = tv[q] > tv[q - 1];
                    float fv = sw ? tv[q - 1] : tv[q];
                    int   fi = sw ? ti[q - 1] : ti[q];
                    tv[q - 1] = sw ? tv[q] : tv[q - 1];
                    ti[q - 1] = sw ? ti[q] : ti[q - 1];
                    tv[q] = fv; ti[q] = fi;
                }
            }
        }
        const size_t tvo = (size_t)Ntok * 64;
        const size_t ixo = tvo + (size_t)Ntok * 8;
        *reinterpret_cast<float4*>(out + tvo + gt * 8)     =
            make_float4(tv[0], tv[1], tv[2], tv[3]);
        *reinterpret_cast<float4*>(out + tvo + gt * 8 + 4) =
            make_float4(tv[4], tv[5], tv[6], tv[7]);
        *reinterpret_cast<float4*>(out + ixo + gt * 8)     =
            make_float4((float)ti[0], (float)ti[1], (float)ti[2], (float)ti[3]);
        *reinterpret_cast<float4*>(out + ixo + gt * 8 + 4) =
            make_float4((float)ti[4], (float)ti[5], (float)ti[6], (float)ti[7]);
    }
}

extern "C" void kernel_launch(void* const* d_in, const int* in_sizes, int n_in,
                              void* d_out, int out_size) {
    const float* x = (const float*)d_in[0];
    const float* w = (const float*)d_in[1];
    float* out = (float*)d_out;
    int Ntok = in_sizes[0] / D;     // 32768

    cudaFuncSetAttribute(moe_gate, cudaFuncAttributeMaxDynamicSharedMemorySize, SMEM_SZ);
    prep_bfrag<<<(256 * 8 * 32 + 255) / 256, 256>>>(w);
    moe_gate<<<Ntok / TB, 256, SMEM_SZ>>>(x, out, Ntok);
}